// round 4
// baseline (speedup 1.0000x reference)
#include <cuda_runtime.h>
#include <cuda_bf16.h>
#include <cstdint>

#define N_NODES 100000
#define N_EDGES 1600000
#define IN_FEAT 128
#define UNITS   64

// ---------------- scratch (device globals: alloc-free rule) ----------------
__device__ float g_h[(size_t)N_NODES * UNITS];       // 25.6 MB
__device__ float g_adst[N_NODES];
__device__ float g_asrc[N_NODES];
__device__ int   g_rowptr[N_NODES + 1];
__device__ float g_p[N_EDGES];                       // exp'd scores, 6.4 MB
__device__ int   g_src[N_EDGES];                     // unpacked src (int32)
__device__ int   g_is64;                             // edge dtype flag

// packed f32x2 helpers (FFMA2 only reachable via PTX)
#define FMA_F32X2(d, a, b, c) \
    asm("fma.rn.f32x2 %0, %1, %2, %3;" : "=l"(d) : "l"(a), "l"(b), "l"(c))
#define PACK_F32X2(out, lo, hi) \
    asm("mov.b64 %0, {%1, %2};" : "=l"(out) : "f"(lo), "f"(hi))
#define UNPACK_F32X2(lo, hi, in) \
    asm("mov.b64 {%0, %1}, %2;" : "=f"(lo), "=f"(hi) : "l"(in))

// ---------------------------------------------------------------------------
// Kernel 0a: detect int64 vs int32 edges. For int64 (< 2^31) every odd
// 32-bit word is a zero high-word; for int32 they are random src ids.
// ---------------------------------------------------------------------------
__global__ void gat_detect_kernel(const unsigned int* __restrict__ e32)
{
    if (threadIdx.x == 0 && blockIdx.x == 0) {
        int all_zero = 1;
        #pragma unroll
        for (int i = 0; i < 32; i++)
            if (e32[2 * i + 1] != 0u) { all_zero = 0; break; }
        g_is64 = all_zero;
    }
}

// ---------------------------------------------------------------------------
// Kernel 0b: unpack src + build CSR rowptr from sorted dst (fused).
// ---------------------------------------------------------------------------
__global__ void gat_unpack_rowptr_kernel(const unsigned int* __restrict__ e32)
{
    int i = blockIdx.x * blockDim.x + threadIdx.x;
    if (i >= N_EDGES) return;
    int d, s, dprev;
    if (g_is64) {
        d = (int)e32[4 * (size_t)i];
        s = (int)e32[4 * (size_t)i + 2];
        dprev = (i == 0) ? -1 : (int)e32[4 * (size_t)(i - 1)];
    } else {
        d = (int)e32[2 * (size_t)i];
        s = (int)e32[2 * (size_t)i + 1];
        dprev = (i == 0) ? -1 : (int)e32[2 * (size_t)(i - 1)];
    }
    g_src[i] = s;
    for (int n = dprev + 1; n <= d; n++) g_rowptr[n] = i;
    if (i == N_EDGES - 1)
        for (int n = d + 1; n <= N_NODES; n++) g_rowptr[n] = N_EDGES;
}

// ---------------------------------------------------------------------------
// Kernel 1: GEMM h = X(100000x128) @ K(128x64) with packed f32x2 FMAs,
// fused a_dst = h.ka[0:64], a_src = h.ka[64:128].
// 256 threads, 32 rows/block; thread microtile = 1 row x 8 cols.
// Per k-step: 2x LDS.128 (kv) + 1 broadcast LDS.32 (xv) + 4 FMA2.
// ---------------------------------------------------------------------------
#define TM 32

__global__ void __launch_bounds__(256, 4)
gat_gemm_kernel(const float* __restrict__ X,
                const float* __restrict__ K,
                const float* __restrict__ KA)
{
    __shared__ float Ks[IN_FEAT * UNITS];   // 32 KB
    __shared__ float Xs[TM * IN_FEAT];      // 16 KB

    const int tid  = threadIdx.x;
    const int row0 = blockIdx.x * TM;

    {
        const float4* K4 = (const float4*)K;
        float4* Ks4 = (float4*)Ks;
        #pragma unroll
        for (int i = tid; i < (IN_FEAT * UNITS) / 4; i += 256)
            Ks4[i] = K4[i];
    }
    {
        const float4* X4 = (const float4*)X;
        float4* Xs4 = (float4*)Xs;
        #pragma unroll
        for (int i = tid; i < TM * (IN_FEAT / 4); i += 256)
            Xs4[i] = X4[(size_t)row0 * (IN_FEAT / 4) + i];
    }
    __syncthreads();

    const int colb = tid & 7;           // 8 col groups of 8 cols
    const int row  = tid >> 3;          // 32 rows, one per thread
    const int c0   = colb * 8;

    unsigned long long acc[4];
    #pragma unroll
    for (int j = 0; j < 4; j++) acc[j] = 0ull;

    #pragma unroll 4
    for (int k = 0; k < IN_FEAT; k++) {
        ulonglong2 kva = *(const ulonglong2*)&Ks[k * UNITS + c0];
        ulonglong2 kvb = *(const ulonglong2*)&Ks[k * UNITS + c0 + 4];
        float xv = Xs[row * IN_FEAT + k];
        unsigned long long xx;
        PACK_F32X2(xx, xv, xv);
        FMA_F32X2(acc[0], xx, kva.x, acc[0]);
        FMA_F32X2(acc[1], xx, kva.y, acc[1]);
        FMA_F32X2(acc[2], xx, kvb.x, acc[2]);
        FMA_F32X2(acc[3], xx, kvb.y, acc[3]);
    }

    // unpack 8 result floats
    float h[8];
    #pragma unroll
    for (int j = 0; j < 4; j++)
        UNPACK_F32X2(h[2 * j], h[2 * j + 1], acc[j]);

    // store h (two float4 per thread, coalesced within warp)
    {
        float* dst = &g_h[(size_t)(row0 + row) * UNITS + c0];
        *(float4*)&dst[0] = make_float4(h[0], h[1], h[2], h[3]);
        *(float4*)&dst[4] = make_float4(h[4], h[5], h[6], h[7]);
    }

    // fused attention logits: partial dot with both ka halves, reduce over
    // the 8 lanes (colb 0..7) that share this row.
    float p0 = 0.f, p1 = 0.f;
    #pragma unroll
    for (int j = 0; j < 8; j++) {
        p0 = fmaf(h[j], KA[c0 + j],         p0);
        p1 = fmaf(h[j], KA[UNITS + c0 + j], p1);
    }
    #pragma unroll
    for (int o = 4; o > 0; o >>= 1) {
        p0 += __shfl_down_sync(0xffffffffu, p0, o, 8);
        p1 += __shfl_down_sync(0xffffffffu, p1, o, 8);
    }
    if (colb == 0) {
        g_adst[row0 + row] = p0;
        g_asrc[row0 + row] = p1;
    }
}

// ---------------------------------------------------------------------------
// Kernel 3: fused edge softmax + weighted scatter. One warp per node.
// Pass A: exp'd scores + warp segment sum. Pass B: unroll-4 prefetched
// gather of h[src] rows (float2 per lane), register accumulation.
// ---------------------------------------------------------------------------
__global__ void __launch_bounds__(256)
gat_attn_kernel(float* __restrict__ out)
{
    int gtid = blockIdx.x * blockDim.x + threadIdx.x;
    int node = gtid >> 5;
    int lane = gtid & 31;
    if (node >= N_NODES) return;

    int start = g_rowptr[node];
    int end   = g_rowptr[node + 1];
    float ad  = g_adst[node];

    // Pass A
    float sum = 0.f;
    for (int e = start + lane; e < end; e += 32) {
        int s = g_src[e];
        float sc = ad + g_asrc[s];
        sc = (sc > 0.f) ? sc : 0.2f * sc;       // leaky_relu(0.2)
        sc = fminf(fmaxf(sc, -2.f), 2.f);       // clip
        float p = __expf(sc);
        g_p[e] = p;
        sum += p;
    }
    #pragma unroll
    for (int o = 16; o > 0; o >>= 1)
        sum += __shfl_xor_sync(0xffffffffu, sum, o);
    __syncwarp();   // order g_p writes before pass B reads

    float inv = (end > start) ? (1.f / sum) : 0.f;

    // Pass B
    float2 a = make_float2(0.f, 0.f);
    const size_t off = 2 * lane;
    int e = start;
    for (; e + 4 <= end; e += 4) {
        int s0 = g_src[e],     s1 = g_src[e + 1];
        int s2 = g_src[e + 2], s3 = g_src[e + 3];
        float w0 = g_p[e]     * inv, w1 = g_p[e + 1] * inv;
        float w2 = g_p[e + 2] * inv, w3 = g_p[e + 3] * inv;
        float2 h0 = *(const float2*)&g_h[(size_t)s0 * UNITS + off];
        float2 h1 = *(const float2*)&g_h[(size_t)s1 * UNITS + off];
        float2 h2 = *(const float2*)&g_h[(size_t)s2 * UNITS + off];
        float2 h3 = *(const float2*)&g_h[(size_t)s3 * UNITS + off];
        a.x = fmaf(h0.x, w0, a.x);  a.y = fmaf(h0.y, w0, a.y);
        a.x = fmaf(h1.x, w1, a.x);  a.y = fmaf(h1.y, w1, a.y);
        a.x = fmaf(h2.x, w2, a.x);  a.y = fmaf(h2.y, w2, a.y);
        a.x = fmaf(h3.x, w3, a.x);  a.y = fmaf(h3.y, w3, a.y);
    }
    for (; e < end; e++) {
        int s = g_src[e];
        float w = g_p[e] * inv;
        float2 h0 = *(const float2*)&g_h[(size_t)s * UNITS + off];
        a.x = fmaf(h0.x, w, a.x);
        a.y = fmaf(h0.y, w, a.y);
    }
    *(float2*)&out[(size_t)node * UNITS + off] = a;
}

// ---------------------------------------------------------------------------
extern "C" void kernel_launch(void* const* d_in, const int* in_sizes, int n_in,
                              void* d_out, int out_size)
{
    const float*        X   = (const float*)d_in[0];        // node_states
    const unsigned int* E32 = (const unsigned int*)d_in[1]; // edges
    const float*        K   = (const float*)d_in[2];        // kernel [128,64]
    const float*        KA  = (const float*)d_in[3];        // kernel_attention
    float*              O   = (float*)d_out;

    gat_detect_kernel<<<1, 32>>>(E32);
    gat_unpack_rowptr_kernel<<<(N_EDGES + 255) / 256, 256>>>(E32);
    gat_gemm_kernel<<<N_NODES / TM, 256>>>(X, K, KA);
    gat_attn_kernel<<<(N_NODES * 32 + 255) / 256, 256>>>(O);
}

// round 5
// speedup vs baseline: 1.9667x; 1.9667x over previous
#include <cuda_runtime.h>
#include <cuda_bf16.h>
#include <cstdint>

#define N_NODES 100000
#define N_EDGES 1600000
#define IN_FEAT 128
#define UNITS   64

// ---------------- scratch (device globals: alloc-free rule) ----------------
__device__ float g_h[(size_t)N_NODES * UNITS];       // 25.6 MB
__device__ float g_adst[N_NODES];
__device__ float g_asrc[N_NODES];
__device__ int   g_rowptr[N_NODES + 1];
__device__ int   g_src[N_EDGES];                     // unpacked src (int32)
__device__ int   g_is64;                             // edge dtype flag

// ---------------------------------------------------------------------------
// Kernel 0a: detect int64 vs int32 edges. For int64 (< 2^31) every odd
// 32-bit word is a zero high-word; for int32 they are random src ids.
// ---------------------------------------------------------------------------
__global__ void gat_detect_kernel(const unsigned int* __restrict__ e32)
{
    if (threadIdx.x == 0 && blockIdx.x == 0) {
        int all_zero = 1;
        #pragma unroll
        for (int i = 0; i < 32; i++)
            if (e32[2 * i + 1] != 0u) { all_zero = 0; break; }
        g_is64 = all_zero;
    }
}

// ---------------------------------------------------------------------------
// Kernel 0b: unpack src + build CSR rowptr from sorted dst (fused).
// ---------------------------------------------------------------------------
__global__ void gat_unpack_rowptr_kernel(const unsigned int* __restrict__ e32)
{
    int i = blockIdx.x * blockDim.x + threadIdx.x;
    if (i >= N_EDGES) return;
    int d, s, dprev;
    if (g_is64) {
        d = (int)e32[4 * (size_t)i];
        s = (int)e32[4 * (size_t)i + 2];
        dprev = (i == 0) ? -1 : (int)e32[4 * (size_t)(i - 1)];
    } else {
        d = (int)e32[2 * (size_t)i];
        s = (int)e32[2 * (size_t)i + 1];
        dprev = (i == 0) ? -1 : (int)e32[2 * (size_t)(i - 1)];
    }
    g_src[i] = s;
    for (int n = dprev + 1; n <= d; n++) g_rowptr[n] = i;
    if (i == N_EDGES - 1)
        for (int n = d + 1; n <= N_NODES; n++) g_rowptr[n] = N_EDGES;
}

// ---------------------------------------------------------------------------
// Kernel 1 (reverted to R3 scalar version): tiled GEMM
// h = X(100000x128) @ K(128x64), fused a_dst/a_src logits.
// 256 threads, 32 rows/block, 2 rows x 4 cols per thread. 48 KB static smem.
// ---------------------------------------------------------------------------
#define TM 32

__global__ void __launch_bounds__(256, 4)
gat_gemm_kernel(const float* __restrict__ X,
                const float* __restrict__ K,
                const float* __restrict__ KA)
{
    __shared__ float Ks[IN_FEAT * UNITS];   // 32 KB
    __shared__ float Xs[TM * IN_FEAT];      // 16 KB

    const int tid  = threadIdx.x;
    const int row0 = blockIdx.x * TM;

    {
        const float4* K4 = (const float4*)K;
        float4* Ks4 = (float4*)Ks;
        #pragma unroll
        for (int i = tid; i < (IN_FEAT * UNITS) / 4; i += 256)
            Ks4[i] = K4[i];
    }
    {
        const float4* X4 = (const float4*)X;
        float4* Xs4 = (float4*)Xs;
        #pragma unroll
        for (int i = tid; i < TM * (IN_FEAT / 4); i += 256)
            Xs4[i] = X4[(size_t)row0 * (IN_FEAT / 4) + i];
    }
    __syncthreads();

    const int colb = tid & 15;          // 16 col groups of 4 cols
    const int rowb = tid >> 4;          // 16 row groups of 2 rows
    const int c0 = colb * 4;
    const int r0 = rowb * 2;

    float acc[2][4];
    #pragma unroll
    for (int r = 0; r < 2; r++)
        #pragma unroll
        for (int c = 0; c < 4; c++)
            acc[r][c] = 0.f;

    #pragma unroll 4
    for (int k = 0; k < IN_FEAT; k++) {
        float4 kv = *(const float4*)&Ks[k * UNITS + c0];
        #pragma unroll
        for (int r = 0; r < 2; r++) {
            float xv = Xs[(r0 + r) * IN_FEAT + k];
            acc[r][0] = fmaf(xv, kv.x, acc[r][0]);
            acc[r][1] = fmaf(xv, kv.y, acc[r][1]);
            acc[r][2] = fmaf(xv, kv.z, acc[r][2]);
            acc[r][3] = fmaf(xv, kv.w, acc[r][3]);
        }
    }

    #pragma unroll
    for (int r = 0; r < 2; r++) {
        int row = row0 + r0 + r;
        float4 v = make_float4(acc[r][0], acc[r][1], acc[r][2], acc[r][3]);
        *(float4*)&g_h[(size_t)row * UNITS + c0] = v;
    }

    // fused attention logits
    float ka0[4], ka1[4];
    #pragma unroll
    for (int j = 0; j < 4; j++) {
        ka0[j] = KA[c0 + j];            // dst half
        ka1[j] = KA[UNITS + c0 + j];    // src half
    }
    #pragma unroll
    for (int r = 0; r < 2; r++) {
        float p0 = acc[r][0] * ka0[0] + acc[r][1] * ka0[1]
                 + acc[r][2] * ka0[2] + acc[r][3] * ka0[3];
        float p1 = acc[r][0] * ka1[0] + acc[r][1] * ka1[1]
                 + acc[r][2] * ka1[2] + acc[r][3] * ka1[3];
        #pragma unroll
        for (int o = 8; o > 0; o >>= 1) {
            p0 += __shfl_down_sync(0xffffffffu, p0, o, 16);
            p1 += __shfl_down_sync(0xffffffffu, p1, o, 16);
        }
        if (colb == 0) {
            int row = row0 + r0 + r;
            g_adst[row] = p0;
            g_asrc[row] = p1;
        }
    }
}

// ---------------------------------------------------------------------------
// Kernel 2: SINGLE-PASS fused softmax + scatter. One warp per node.
// out = (sum_e p_e * h[src_e]) / (sum_e p_e): normalization commutes with
// accumulation, so no score array and no second pass. p computed inline
// (warp-uniform), h row gathered as float2/lane, unroll-4 prefetch.
// ---------------------------------------------------------------------------
__global__ void __launch_bounds__(256)
gat_attn_kernel(float* __restrict__ out)
{
    int gtid = blockIdx.x * blockDim.x + threadIdx.x;
    int node = gtid >> 5;
    int lane = gtid & 31;
    if (node >= N_NODES) return;

    int start = g_rowptr[node];
    int end   = g_rowptr[node + 1];
    float ad  = g_adst[node];

    const size_t off = 2 * lane;
    float2 a = make_float2(0.f, 0.f);
    float sum = 0.f;

    int e = start;
    for (; e + 4 <= end; e += 4) {
        int s0 = g_src[e],     s1 = g_src[e + 1];
        int s2 = g_src[e + 2], s3 = g_src[e + 3];
        float as0 = g_asrc[s0], as1 = g_asrc[s1];
        float as2 = g_asrc[s2], as3 = g_asrc[s3];
        float2 h0 = *(const float2*)&g_h[(size_t)s0 * UNITS + off];
        float2 h1 = *(const float2*)&g_h[(size_t)s1 * UNITS + off];
        float2 h2 = *(const float2*)&g_h[(size_t)s2 * UNITS + off];
        float2 h3 = *(const float2*)&g_h[(size_t)s3 * UNITS + off];

        float sc0 = ad + as0; sc0 = (sc0 > 0.f) ? sc0 : 0.2f * sc0;
        float sc1 = ad + as1; sc1 = (sc1 > 0.f) ? sc1 : 0.2f * sc1;
        float sc2 = ad + as2; sc2 = (sc2 > 0.f) ? sc2 : 0.2f * sc2;
        float sc3 = ad + as3; sc3 = (sc3 > 0.f) ? sc3 : 0.2f * sc3;
        float p0 = __expf(fminf(fmaxf(sc0, -2.f), 2.f));
        float p1 = __expf(fminf(fmaxf(sc1, -2.f), 2.f));
        float p2 = __expf(fminf(fmaxf(sc2, -2.f), 2.f));
        float p3 = __expf(fminf(fmaxf(sc3, -2.f), 2.f));

        sum += (p0 + p1) + (p2 + p3);
        a.x = fmaf(h0.x, p0, a.x);  a.y = fmaf(h0.y, p0, a.y);
        a.x = fmaf(h1.x, p1, a.x);  a.y = fmaf(h1.y, p1, a.y);
        a.x = fmaf(h2.x, p2, a.x);  a.y = fmaf(h2.y, p2, a.y);
        a.x = fmaf(h3.x, p3, a.x);  a.y = fmaf(h3.y, p3, a.y);
    }
    for (; e < end; e++) {
        int s = g_src[e];
        float sc = ad + g_asrc[s];
        sc = (sc > 0.f) ? sc : 0.2f * sc;
        float p = __expf(fminf(fmaxf(sc, -2.f), 2.f));
        float2 h0 = *(const float2*)&g_h[(size_t)s * UNITS + off];
        sum += p;
        a.x = fmaf(h0.x, p, a.x);
        a.y = fmaf(h0.y, p, a.y);
    }

    float inv = (end > start) ? (1.f / sum) : 0.f;
    float2 r = make_float2(a.x * inv, a.y * inv);
    *(float2*)&out[(size_t)node * UNITS + off] = r;
}

// ---------------------------------------------------------------------------
extern "C" void kernel_launch(void* const* d_in, const int* in_sizes, int n_in,
                              void* d_out, int out_size)
{
    const float*        X   = (const float*)d_in[0];        // node_states
    const unsigned int* E32 = (const unsigned int*)d_in[1]; // edges
    const float*        K   = (const float*)d_in[2];        // kernel [128,64]
    const float*        KA  = (const float*)d_in[3];        // kernel_attention
    float*              O   = (float*)d_out;

    gat_detect_kernel<<<1, 32>>>(E32);
    gat_unpack_rowptr_kernel<<<(N_EDGES + 255) / 256, 256>>>(E32);
    gat_gemm_kernel<<<N_NODES / TM, 256>>>(X, K, KA);
    gat_attn_kernel<<<(N_NODES * 32 + 255) / 256, 256>>>(O);
}

// round 6
// speedup vs baseline: 2.0263x; 1.0303x over previous
#include <cuda_runtime.h>
#include <cuda_fp16.h>
#include <cstdint>

#define N_NODES 100000
#define N_EDGES 1600000
#define IN_FEAT 128
#define UNITS   64

// ---------------- scratch (device globals: alloc-free rule) ----------------
__device__ __half g_h16[(size_t)N_NODES * UNITS];    // 12.8 MB (fp16 h)
__device__ float  g_adst[N_NODES];
__device__ float  g_asrc[N_NODES];
__device__ int    g_rowptr[N_NODES + 1];
__device__ int    g_dst[N_EDGES];
__device__ int    g_src[N_EDGES];
__device__ float  g_p[N_EDGES];                      // exp'd scores
__device__ int    g_is64;

// ---------------------------------------------------------------------------
// Kernel 0a: detect int64 vs int32 edges (odd words all-zero => int64).
// ---------------------------------------------------------------------------
__global__ void gat_detect_kernel(const unsigned int* __restrict__ e32)
{
    if (threadIdx.x == 0 && blockIdx.x == 0) {
        int all_zero = 1;
        #pragma unroll
        for (int i = 0; i < 32; i++)
            if (e32[2 * i + 1] != 0u) { all_zero = 0; break; }
        g_is64 = all_zero;
    }
}

// ---------------------------------------------------------------------------
// Kernel 0b: unpack dst/src + build CSR rowptr from sorted dst (fused).
// ---------------------------------------------------------------------------
__global__ void gat_unpack_rowptr_kernel(const unsigned int* __restrict__ e32)
{
    int i = blockIdx.x * blockDim.x + threadIdx.x;
    if (i >= N_EDGES) return;
    int d, s, dprev;
    if (g_is64) {
        d = (int)e32[4 * (size_t)i];
        s = (int)e32[4 * (size_t)i + 2];
        dprev = (i == 0) ? -1 : (int)e32[4 * (size_t)(i - 1)];
    } else {
        d = (int)e32[2 * (size_t)i];
        s = (int)e32[2 * (size_t)i + 1];
        dprev = (i == 0) ? -1 : (int)e32[2 * (size_t)(i - 1)];
    }
    g_dst[i] = d;
    g_src[i] = s;
    for (int n = dprev + 1; n <= d; n++) g_rowptr[n] = i;
    if (i == N_EDGES - 1)
        for (int n = d + 1; n <= N_NODES; n++) g_rowptr[n] = N_EDGES;
}

// ---------------------------------------------------------------------------
// Kernel 1: tiled GEMM h = X @ K (fp32 accum), fused a_dst/a_src logits
// (fp32), h stored quantized to fp16 for the gather stage.
// 256 threads, 32 rows/block, 2 rows x 4 cols per thread, 48 KB static smem.
// ---------------------------------------------------------------------------
#define TM 32

__global__ void __launch_bounds__(256, 4)
gat_gemm_kernel(const float* __restrict__ X,
                const float* __restrict__ K,
                const float* __restrict__ KA)
{
    __shared__ float Ks[IN_FEAT * UNITS];   // 32 KB
    __shared__ float Xs[TM * IN_FEAT];      // 16 KB

    const int tid  = threadIdx.x;
    const int row0 = blockIdx.x * TM;

    {
        const float4* K4 = (const float4*)K;
        float4* Ks4 = (float4*)Ks;
        #pragma unroll
        for (int i = tid; i < (IN_FEAT * UNITS) / 4; i += 256)
            Ks4[i] = K4[i];
    }
    {
        const float4* X4 = (const float4*)X;
        float4* Xs4 = (float4*)Xs;
        #pragma unroll
        for (int i = tid; i < TM * (IN_FEAT / 4); i += 256)
            Xs4[i] = X4[(size_t)row0 * (IN_FEAT / 4) + i];
    }
    __syncthreads();

    const int colb = tid & 15;          // 16 col groups of 4 cols
    const int rowb = tid >> 4;          // 16 row groups of 2 rows
    const int c0 = colb * 4;
    const int r0 = rowb * 2;

    float acc[2][4];
    #pragma unroll
    for (int r = 0; r < 2; r++)
        #pragma unroll
        for (int c = 0; c < 4; c++)
            acc[r][c] = 0.f;

    #pragma unroll 4
    for (int k = 0; k < IN_FEAT; k++) {
        float4 kv = *(const float4*)&Ks[k * UNITS + c0];
        #pragma unroll
        for (int r = 0; r < 2; r++) {
            float xv = Xs[(r0 + r) * IN_FEAT + k];
            acc[r][0] = fmaf(xv, kv.x, acc[r][0]);
            acc[r][1] = fmaf(xv, kv.y, acc[r][1]);
            acc[r][2] = fmaf(xv, kv.z, acc[r][2]);
            acc[r][3] = fmaf(xv, kv.w, acc[r][3]);
        }
    }

    // store h as fp16 (4 halves = 8 B per thread-row, coalesced)
    #pragma unroll
    for (int r = 0; r < 2; r++) {
        int row = row0 + r0 + r;
        half2 lo = __floats2half2_rn(acc[r][0], acc[r][1]);
        half2 hi = __floats2half2_rn(acc[r][2], acc[r][3]);
        half2* dst = (half2*)&g_h16[(size_t)row * UNITS + c0];
        dst[0] = lo;
        dst[1] = hi;
    }

    // fused attention logits (fp32 accumulators — full precision)
    float ka0[4], ka1[4];
    #pragma unroll
    for (int j = 0; j < 4; j++) {
        ka0[j] = KA[c0 + j];            // dst half
        ka1[j] = KA[UNITS + c0 + j];    // src half
    }
    #pragma unroll
    for (int r = 0; r < 2; r++) {
        float p0 = acc[r][0] * ka0[0] + acc[r][1] * ka0[1]
                 + acc[r][2] * ka0[2] + acc[r][3] * ka0[3];
        float p1 = acc[r][0] * ka1[0] + acc[r][1] * ka1[1]
                 + acc[r][2] * ka1[2] + acc[r][3] * ka1[3];
        #pragma unroll
        for (int o = 8; o > 0; o >>= 1) {
            p0 += __shfl_down_sync(0xffffffffu, p0, o, 16);
            p1 += __shfl_down_sync(0xffffffffu, p1, o, 16);
        }
        if (colb == 0) {
            int row = row0 + r0 + r;
            g_adst[row] = p0;
            g_asrc[row] = p1;
        }
    }
}

// ---------------------------------------------------------------------------
// Kernel 2: edge-parallel score kernel. Coalesced over edges; adst/asrc
// (800 KB total) are L2-resident random reads.
// ---------------------------------------------------------------------------
__global__ void __launch_bounds__(256)
gat_score_kernel()
{
    int i = blockIdx.x * blockDim.x + threadIdx.x;
    if (i >= N_EDGES) return;
    float sc = g_adst[g_dst[i]] + g_asrc[g_src[i]];
    sc = (sc > 0.f) ? sc : 0.2f * sc;           // leaky_relu(0.2)
    sc = fminf(fmaxf(sc, -2.f), 2.f);           // clip
    g_p[i] = __expf(sc);
}

// ---------------------------------------------------------------------------
// Kernel 3: gather-only segment reduce. One warp per node.
// out = (sum_e p_e * h[src_e]) / (sum_e p_e). Each lane holds 2 columns
// (one half2 = 4 B -> warp gather is exactly one 128 B line per edge).
// ---------------------------------------------------------------------------
__global__ void __launch_bounds__(256)
gat_gather_kernel(float* __restrict__ out)
{
    int gtid = blockIdx.x * blockDim.x + threadIdx.x;
    int node = gtid >> 5;
    int lane = gtid & 31;
    if (node >= N_NODES) return;

    int start = g_rowptr[node];
    int end   = g_rowptr[node + 1];

    float2 a = make_float2(0.f, 0.f);
    float sum = 0.f;
    const size_t off = 2 * lane;

    int e = start;
    for (; e + 4 <= end; e += 4) {
        int s0 = g_src[e],     s1 = g_src[e + 1];
        int s2 = g_src[e + 2], s3 = g_src[e + 3];
        float p0 = g_p[e],     p1 = g_p[e + 1];
        float p2 = g_p[e + 2], p3 = g_p[e + 3];
        half2 v0 = *(const half2*)&g_h16[(size_t)s0 * UNITS + off];
        half2 v1 = *(const half2*)&g_h16[(size_t)s1 * UNITS + off];
        half2 v2 = *(const half2*)&g_h16[(size_t)s2 * UNITS + off];
        half2 v3 = *(const half2*)&g_h16[(size_t)s3 * UNITS + off];
        float2 h0 = __half22float2(v0);
        float2 h1 = __half22float2(v1);
        float2 h2 = __half22float2(v2);
        float2 h3 = __half22float2(v3);
        sum += (p0 + p1) + (p2 + p3);
        a.x = fmaf(h0.x, p0, a.x);  a.y = fmaf(h0.y, p0, a.y);
        a.x = fmaf(h1.x, p1, a.x);  a.y = fmaf(h1.y, p1, a.y);
        a.x = fmaf(h2.x, p2, a.x);  a.y = fmaf(h2.y, p2, a.y);
        a.x = fmaf(h3.x, p3, a.x);  a.y = fmaf(h3.y, p3, a.y);
    }
    for (; e < end; e++) {
        int s = g_src[e];
        float p = g_p[e];
        float2 h0 = __half22float2(*(const half2*)&g_h16[(size_t)s * UNITS + off]);
        sum += p;
        a.x = fmaf(h0.x, p, a.x);
        a.y = fmaf(h0.y, p, a.y);
    }

    float inv = (end > start) ? (1.f / sum) : 0.f;
    float2 r = make_float2(a.x * inv, a.y * inv);
    *(float2*)&out[(size_t)node * UNITS + off] = r;
}

// ---------------------------------------------------------------------------
extern "C" void kernel_launch(void* const* d_in, const int* in_sizes, int n_in,
                              void* d_out, int out_size)
{
    const float*        X   = (const float*)d_in[0];        // node_states
    const unsigned int* E32 = (const unsigned int*)d_in[1]; // edges
    const float*        K   = (const float*)d_in[2];        // kernel [128,64]
    const float*        KA  = (const float*)d_in[3];        // kernel_attention
    float*              O   = (float*)d_out;

    gat_detect_kernel<<<1, 32>>>(E32);
    gat_unpack_rowptr_kernel<<<(N_EDGES + 255) / 256, 256>>>(E32);
    gat_gemm_kernel<<<N_NODES / TM, 256>>>(X, K, KA);
    gat_score_kernel<<<(N_EDGES + 255) / 256, 256>>>();
    gat_gather_kernel<<<(N_NODES * 32 + 255) / 256, 256>>>(O);
}

// round 7
// speedup vs baseline: 2.2552x; 1.1129x over previous
#include <cuda_runtime.h>
#include <cuda_fp16.h>
#include <cstdint>

#define N_NODES 100000
#define N_EDGES 1600000
#define IN_FEAT 128
#define UNITS   64

// ---------------- scratch (device globals: alloc-free rule) ----------------
__device__ __half g_h16[(size_t)N_NODES * UNITS];    // 12.8 MB
__device__ float  g_adst[N_NODES];
__device__ float  g_asrc[N_NODES];
__device__ int    g_rowptr[N_NODES + 1];
__device__ int    g_dst[N_EDGES];
__device__ int    g_src[N_EDGES];
__device__ float  g_p[N_EDGES];
__device__ int    g_is64;

// ---------------------------------------------------------------------------
// Kernel 0a: detect int64 vs int32 edges (odd words all-zero => int64).
// ---------------------------------------------------------------------------
__global__ void gat_detect_kernel(const unsigned int* __restrict__ e32)
{
    if (threadIdx.x == 0 && blockIdx.x == 0) {
        int all_zero = 1;
        #pragma unroll
        for (int i = 0; i < 32; i++)
            if (e32[2 * i + 1] != 0u) { all_zero = 0; break; }
        g_is64 = all_zero;
    }
}

// ---------------------------------------------------------------------------
// Kernel 0b: unpack dst/src + build CSR rowptr from sorted dst (fused).
// ---------------------------------------------------------------------------
__global__ void gat_unpack_rowptr_kernel(const unsigned int* __restrict__ e32)
{
    int i = blockIdx.x * blockDim.x + threadIdx.x;
    if (i >= N_EDGES) return;
    int d, s, dprev;
    if (g_is64) {
        d = (int)e32[4 * (size_t)i];
        s = (int)e32[4 * (size_t)i + 2];
        dprev = (i == 0) ? -1 : (int)e32[4 * (size_t)(i - 1)];
    } else {
        d = (int)e32[2 * (size_t)i];
        s = (int)e32[2 * (size_t)i + 1];
        dprev = (i == 0) ? -1 : (int)e32[2 * (size_t)(i - 1)];
    }
    g_dst[i] = d;
    g_src[i] = s;
    for (int n = dprev + 1; n <= d; n++) g_rowptr[n] = i;
    if (i == N_EDGES - 1)
        for (int n = d + 1; n <= N_NODES; n++) g_rowptr[n] = N_EDGES;
}

// ---------------------------------------------------------------------------
// Kernel 1: HMMA GEMM h = X(100000x128) @ K(128x64), fp16 in / fp32 acc.
// Block = 128 thr (4 warps), M-tile 64. Fused adst/asrc logits in epilogue.
// A smem: [64][130] halfs (row-major, K contiguous). B smem: [64][130]
// halfs TRANSPOSED (Bs[n][k]) so mma b-fragments are contiguous 32-bit LDS.
// ---------------------------------------------------------------------------
#define MT 64
#define APAD 130

__global__ void __launch_bounds__(128, 4)
gat_gemm_kernel(const float* __restrict__ X,
                const float* __restrict__ K,
                const float* __restrict__ KA)
{
    __shared__ __half As[MT * APAD];        // 16.6 KB
    __shared__ __half Bs[UNITS * APAD];     // 16.6 KB

    const int tid  = threadIdx.x;
    const int row0 = blockIdx.x * MT;

    // stage B transposed: K[k][n] fp32 -> Bs[n][k] fp16 (coalesced reads)
    for (int i = tid; i < IN_FEAT * UNITS; i += 128) {
        int k = i >> 6;          // 0..127
        int n = i & 63;          // 0..63
        Bs[n * APAD + k] = __float2half_rn(K[i]);
    }
    // stage A: X rows row0..row0+63 fp32 -> fp16 (float4 loads)
    for (int i = tid; i < MT * (IN_FEAT / 4); i += 128) {
        int r  = i >> 5;         // 32 float4 per row
        int c4 = i & 31;
        float4 v = (row0 + r < N_NODES)
                 ? *(const float4*)&X[(size_t)(row0 + r) * IN_FEAT + c4 * 4]
                 : make_float4(0.f, 0.f, 0.f, 0.f);
        __half* dst = &As[r * APAD + c4 * 4];
        dst[0] = __float2half_rn(v.x);
        dst[1] = __float2half_rn(v.y);
        dst[2] = __float2half_rn(v.z);
        dst[3] = __float2half_rn(v.w);
    }
    __syncthreads();

    const int warp = tid >> 5;           // 4 warps: rows 16*warp..+15
    const int lane = tid & 31;
    const int grp  = lane >> 2;          // 0..7
    const int tig  = lane & 3;           // 0..3

    float c[8][4];                       // 8 n-chunks x 4 accum
    #pragma unroll
    for (int i = 0; i < 8; i++)
        #pragma unroll
        for (int j = 0; j < 4; j++) c[i][j] = 0.f;

    const int ar0 = warp * 16 + grp;     // fragment row (tile-local)
    #pragma unroll
    for (int ks = 0; ks < 8; ks++) {
        const int kb = ks * 16;
        unsigned a0 = *(const unsigned*)&As[ar0 * APAD + kb + 2 * tig];
        unsigned a1 = *(const unsigned*)&As[(ar0 + 8) * APAD + kb + 2 * tig];
        unsigned a2 = *(const unsigned*)&As[ar0 * APAD + kb + 2 * tig + 8];
        unsigned a3 = *(const unsigned*)&As[(ar0 + 8) * APAD + kb + 2 * tig + 8];
        #pragma unroll
        for (int n = 0; n < 8; n++) {
            unsigned b0 = *(const unsigned*)&Bs[(n * 8 + grp) * APAD + kb + 2 * tig];
            unsigned b1 = *(const unsigned*)&Bs[(n * 8 + grp) * APAD + kb + 2 * tig + 8];
            asm volatile(
                "mma.sync.aligned.m16n8k16.row.col.f32.f16.f16.f32 "
                "{%0,%1,%2,%3}, {%4,%5,%6,%7}, {%8,%9}, {%0,%1,%2,%3};"
                : "+f"(c[n][0]), "+f"(c[n][1]), "+f"(c[n][2]), "+f"(c[n][3])
                : "r"(a0), "r"(a1), "r"(a2), "r"(a3), "r"(b0), "r"(b1));
        }
    }

    // epilogue: rows r0 = row0+16*warp+grp, r1 = r0+8; cols 8n+2*tig, +1
    const int rA = row0 + warp * 16 + grp;
    const int rB = rA + 8;
    float pa0 = 0.f, pa1 = 0.f;   // logits for row rA (dst-half, src-half)
    float pb0 = 0.f, pb1 = 0.f;   // logits for row rB
    #pragma unroll
    for (int n = 0; n < 8; n++) {
        const int col = n * 8 + 2 * tig;
        float k0d = KA[col],         k1d = KA[col + 1];
        float k0s = KA[UNITS + col], k1s = KA[UNITS + col + 1];
        pa0 = fmaf(c[n][0], k0d, fmaf(c[n][1], k1d, pa0));
        pa1 = fmaf(c[n][0], k0s, fmaf(c[n][1], k1s, pa1));
        pb0 = fmaf(c[n][2], k0d, fmaf(c[n][3], k1d, pb0));
        pb1 = fmaf(c[n][2], k0s, fmaf(c[n][3], k1s, pb1));
        if (rA < N_NODES)
            *(half2*)&g_h16[(size_t)rA * UNITS + col] = __floats2half2_rn(c[n][0], c[n][1]);
        if (rB < N_NODES)
            *(half2*)&g_h16[(size_t)rB * UNITS + col] = __floats2half2_rn(c[n][2], c[n][3]);
    }
    // reduce over the 4 lanes (tig 0..3) sharing each row
    #pragma unroll
    for (int o = 2; o > 0; o >>= 1) {
        pa0 += __shfl_down_sync(0xffffffffu, pa0, o, 4);
        pa1 += __shfl_down_sync(0xffffffffu, pa1, o, 4);
        pb0 += __shfl_down_sync(0xffffffffu, pb0, o, 4);
        pb1 += __shfl_down_sync(0xffffffffu, pb1, o, 4);
    }
    if (tig == 0) {
        if (rA < N_NODES) { g_adst[rA] = pa0; g_asrc[rA] = pa1; }
        if (rB < N_NODES) { g_adst[rB] = pb0; g_asrc[rB] = pb1; }
    }
}

// ---------------------------------------------------------------------------
// Kernel 2: edge-parallel scores, 4 edges/thread (int4 loads, 8 gathers
// in flight, float4 store) to beat the latency bound.
// ---------------------------------------------------------------------------
__global__ void __launch_bounds__(256)
gat_score_kernel()
{
    int t = blockIdx.x * blockDim.x + threadIdx.x;
    int base = t * 4;
    if (base >= N_EDGES) return;
    int4 d = *(const int4*)&g_dst[base];
    int4 s = *(const int4*)&g_src[base];
    float sc0 = g_adst[d.x] + g_asrc[s.x];
    float sc1 = g_adst[d.y] + g_asrc[s.y];
    float sc2 = g_adst[d.z] + g_asrc[s.z];
    float sc3 = g_adst[d.w] + g_asrc[s.w];
    sc0 = (sc0 > 0.f) ? sc0 : 0.2f * sc0;
    sc1 = (sc1 > 0.f) ? sc1 : 0.2f * sc1;
    sc2 = (sc2 > 0.f) ? sc2 : 0.2f * sc2;
    sc3 = (sc3 > 0.f) ? sc3 : 0.2f * sc3;
    float4 p;
    p.x = __expf(fminf(fmaxf(sc0, -2.f), 2.f));
    p.y = __expf(fminf(fmaxf(sc1, -2.f), 2.f));
    p.z = __expf(fminf(fmaxf(sc2, -2.f), 2.f));
    p.w = __expf(fminf(fmaxf(sc3, -2.f), 2.f));
    *(float4*)&g_p[base] = p;
}

// ---------------------------------------------------------------------------
// Kernel 3: gather-only segment reduce. One warp per node; half2 per lane
// => one 128 B line per edge per warp.
// ---------------------------------------------------------------------------
__global__ void __launch_bounds__(256)
gat_gather_kernel(float* __restrict__ out)
{
    int gtid = blockIdx.x * blockDim.x + threadIdx.x;
    int node = gtid >> 5;
    int lane = gtid & 31;
    if (node >= N_NODES) return;

    int start = g_rowptr[node];
    int end   = g_rowptr[node + 1];

    float2 a = make_float2(0.f, 0.f);
    float sum = 0.f;
    const size_t off = 2 * lane;

    int e = start;
    for (; e + 4 <= end; e += 4) {
        int s0 = g_src[e],     s1 = g_src[e + 1];
        int s2 = g_src[e + 2], s3 = g_src[e + 3];
        float p0 = g_p[e],     p1 = g_p[e + 1];
        float p2 = g_p[e + 2], p3 = g_p[e + 3];
        float2 h0 = __half22float2(*(const half2*)&g_h16[(size_t)s0 * UNITS + off]);
        float2 h1 = __half22float2(*(const half2*)&g_h16[(size_t)s1 * UNITS + off]);
        float2 h2 = __half22float2(*(const half2*)&g_h16[(size_t)s2 * UNITS + off]);
        float2 h3 = __half22float2(*(const half2*)&g_h16[(size_t)s3 * UNITS + off]);
        sum += (p0 + p1) + (p2 + p3);
        a.x = fmaf(h0.x, p0, a.x);  a.y = fmaf(h0.y, p0, a.y);
        a.x = fmaf(h1.x, p1, a.x);  a.y = fmaf(h1.y, p1, a.y);
        a.x = fmaf(h2.x, p2, a.x);  a.y = fmaf(h2.y, p2, a.y);
        a.x = fmaf(h3.x, p3, a.x);  a.y = fmaf(h3.y, p3, a.y);
    }
    for (; e < end; e++) {
        int s = g_src[e];
        float p = g_p[e];
        float2 h0 = __half22float2(*(const half2*)&g_h16[(size_t)s * UNITS + off]);
        sum += p;
        a.x = fmaf(h0.x, p, a.x);
        a.y = fmaf(h0.y, p, a.y);
    }

    float inv = (end > start) ? (1.f / sum) : 0.f;
    float2 r = make_float2(a.x * inv, a.y * inv);
    *(float2*)&out[(size_t)node * UNITS + off] = r;
}

// ---------------------------------------------------------------------------
extern "C" void kernel_launch(void* const* d_in, const int* in_sizes, int n_in,
                              void* d_out, int out_size)
{
    const float*        X   = (const float*)d_in[0];
    const unsigned int* E32 = (const unsigned int*)d_in[1];
    const float*        K   = (const float*)d_in[2];
    const float*        KA  = (const float*)d_in[3];
    float*              O   = (float*)d_out;

    gat_detect_kernel<<<1, 32>>>(E32);
    gat_unpack_rowptr_kernel<<<(N_EDGES + 255) / 256, 256>>>(E32);
    gat_gemm_kernel<<<(N_NODES + MT - 1) / MT, 128>>>(X, K, KA);
    gat_score_kernel<<<(N_EDGES / 4 + 255) / 256, 256>>>();
    gat_gather_kernel<<<(N_NODES * 32 + 255) / 256, 256>>>(O);
}

// round 8
// speedup vs baseline: 3.3809x; 1.4992x over previous
#include <cuda_runtime.h>
#include <cuda_fp16.h>
#include <cstdint>

#define N_NODES 100000
#define N_EDGES 1600000
#define IN_FEAT 128
#define UNITS   64

// ---------------- scratch (device globals: alloc-free rule) ----------------
__device__ __align__(16) __half g_h16[(size_t)N_NODES * UNITS]; // 12.8 MB
__device__ __align__(16) __half g_Bt[UNITS * IN_FEAT];          // K^T fp16
__device__ float  g_adst[N_NODES];
__device__ float  g_asrc[N_NODES];
__device__ int    g_rowptr[N_NODES + 1];
__device__ int    g_src[N_EDGES];
__device__ int    g_is64;

// ---------------------------------------------------------------------------
// Kernel 0a: detect int64 vs int32 edges (odd words all-zero => int64).
// ---------------------------------------------------------------------------
__global__ void gat_detect_kernel(const unsigned int* __restrict__ e32)
{
    if (threadIdx.x == 0 && blockIdx.x == 0) {
        int all_zero = 1;
        #pragma unroll
        for (int i = 0; i < 32; i++)
            if (e32[2 * i + 1] != 0u) { all_zero = 0; break; }
        g_is64 = all_zero;
    }
}

// ---------------------------------------------------------------------------
// Kernel 0b: one-time K transpose -> fp16 g_Bt[n][k]  (64 x 128).
// ---------------------------------------------------------------------------
__global__ void gat_prep_bt(const float* __restrict__ K)
{
    int t = blockIdx.x * blockDim.x + threadIdx.x;   // 4096 threads
    if (t >= UNITS * (IN_FEAT / 2)) return;
    int n  = t >> 6;
    int k2 = (t & 63) * 2;
    half2 v = __floats2half2_rn(K[(size_t)k2 * UNITS + n],
                                K[(size_t)(k2 + 1) * UNITS + n]);
    *(half2*)&g_Bt[n * IN_FEAT + k2] = v;
}

// ---------------------------------------------------------------------------
// Kernel 0c: unpack src + CSR rowptr. Vectorized edge load + shfl for the
// predecessor (1 LDG per edge instead of 3). N_EDGES % 256 == 0.
// ---------------------------------------------------------------------------
__global__ void gat_unpack_rowptr_kernel(const unsigned int* __restrict__ e32)
{
    int i = blockIdx.x * blockDim.x + threadIdx.x;
    if (i >= N_EDGES) return;
    int d, s;
    const int is64 = g_is64;
    if (is64) {
        int4 v = *(const int4*)&e32[4 * (size_t)i];
        d = v.x; s = v.z;
    } else {
        int2 v = *(const int2*)&e32[2 * (size_t)i];
        d = v.x; s = v.y;
    }
    g_src[i] = s;
    int dprev = __shfl_up_sync(0xffffffffu, d, 1);
    if ((threadIdx.x & 31) == 0) {
        if (i == 0) dprev = -1;
        else dprev = is64 ? (int)e32[4 * (size_t)(i - 1)]
                          : (int)e32[2 * (size_t)(i - 1)];
    }
    for (int n = dprev + 1; n <= d; n++) g_rowptr[n] = i;
    if (i == N_EDGES - 1)
        for (int n = d + 1; n <= N_NODES; n++) g_rowptr[n] = N_EDGES;
}

// ---------------------------------------------------------------------------
// Kernel 1: HMMA GEMM h = X @ K, fp16 in / fp32 acc. 256 thr (8 warps),
// M-tile 64; warps split N (4 n-chunks each). APAD=136 halves => 68 words
// per row => bank = 4*grp + tig, conflict-free fragment loads.
// Epilogue stages h in smem (coalesced 32B global stores) and computes the
// fused adst/asrc logits from the staged fp16 h.
// ---------------------------------------------------------------------------
#define MT 64
#define APAD 136

__global__ void __launch_bounds__(256)
gat_gemm_kernel(const float* __restrict__ X,
                const float* __restrict__ KA)
{
    __shared__ __half As[MT * APAD];        // 17.4 KB (reused as h staging)
    __shared__ __half Bs[UNITS * APAD];     // 17.4 KB
    __shared__ float  KAs[2 * UNITS];

    const int tid  = threadIdx.x;
    const int row0 = blockIdx.x * MT;

    if (tid < 2 * UNITS) KAs[tid] = KA[tid];

    // stage Bs[n][k] from pre-transposed fp16 g_Bt (float4 = 8 halves)
    {
        const float4* B4 = (const float4*)g_Bt;
        #pragma unroll
        for (int i = tid; i < UNITS * (IN_FEAT / 8); i += 256) {
            int r = i >> 4;             // 16 float4 per row
            int c = i & 15;
            *(float4*)&Bs[r * APAD + c * 8] = B4[i];
        }
    }
    // stage As: X rows -> fp16
    #pragma unroll
    for (int i = tid; i < MT * (IN_FEAT / 4); i += 256) {
        int r  = i >> 5;
        int c4 = i & 31;
        float4 v = (row0 + r < N_NODES)
                 ? *(const float4*)&X[(size_t)(row0 + r) * IN_FEAT + c4 * 4]
                 : make_float4(0.f, 0.f, 0.f, 0.f);
        half2 h01 = __floats2half2_rn(v.x, v.y);
        half2 h23 = __floats2half2_rn(v.z, v.w);
        half2* dst = (half2*)&As[r * APAD + c4 * 4];
        dst[0] = h01;
        dst[1] = h23;
    }
    __syncthreads();

    const int warp = tid >> 5;
    const int lane = tid & 31;
    const int wr   = warp & 3;          // row quarter: rows 16*wr..+15
    const int wn   = warp >> 2;         // n half: chunks 4*wn..4*wn+3
    const int grp  = lane >> 2;
    const int tig  = lane & 3;

    float c[4][4];
    #pragma unroll
    for (int i = 0; i < 4; i++)
        #pragma unroll
        for (int j = 0; j < 4; j++) c[i][j] = 0.f;

    const int ar0 = wr * 16 + grp;
    #pragma unroll
    for (int ks = 0; ks < 8; ks++) {
        const int kb = ks * 16;
        unsigned a0 = *(const unsigned*)&As[ar0 * APAD + kb + 2 * tig];
        unsigned a1 = *(const unsigned*)&As[(ar0 + 8) * APAD + kb + 2 * tig];
        unsigned a2 = *(const unsigned*)&As[ar0 * APAD + kb + 2 * tig + 8];
        unsigned a3 = *(const unsigned*)&As[(ar0 + 8) * APAD + kb + 2 * tig + 8];
        #pragma unroll
        for (int j = 0; j < 4; j++) {
            const int brow = wn * 32 + j * 8 + grp;
            unsigned b0 = *(const unsigned*)&Bs[brow * APAD + kb + 2 * tig];
            unsigned b1 = *(const unsigned*)&Bs[brow * APAD + kb + 2 * tig + 8];
            asm volatile(
                "mma.sync.aligned.m16n8k16.row.col.f32.f16.f16.f32 "
                "{%0,%1,%2,%3}, {%4,%5,%6,%7}, {%8,%9}, {%0,%1,%2,%3};"
                : "+f"(c[j][0]), "+f"(c[j][1]), "+f"(c[j][2]), "+f"(c[j][3])
                : "r"(a0), "r"(a1), "r"(a2), "r"(a3), "r"(b0), "r"(b1));
        }
    }

    // stage h into smem (reusing As) as half2 with stride 36 (conflict-free)
    __syncthreads();                     // all MMA reads of As done
    half2* Hs2 = (half2*)As;
    #pragma unroll
    for (int j = 0; j < 4; j++) {
        const int hc = (wn * 4 + j) * 4 + tig;        // half2 col index
        Hs2[(wr * 16 + grp) * 36 + hc]     = __floats2half2_rn(c[j][0], c[j][1]);
        Hs2[(wr * 16 + grp + 8) * 36 + hc] = __floats2half2_rn(c[j][2], c[j][3]);
    }
    __syncthreads();

    // epilogue: 4 threads per row; 16 cols each. Coalesced 32B h16 stores
    // + fused logits from staged h.
    {
        const int row = tid >> 2;        // 0..63
        const int q   = tid & 3;         // col quarter (16 cols)
        const int gr  = row0 + row;
        uint4 w0 = *(const uint4*)&Hs2[row * 36 + q * 8];
        uint4 w1 = *(const uint4*)&Hs2[row * 36 + q * 8 + 4];
        if (gr < N_NODES) {
            uint4* gdst = (uint4*)&g_h16[(size_t)gr * UNITS + q * 16];
            gdst[0] = w0;
            gdst[1] = w1;
        }
        // logits over this thread's 16 cols
        float pd = 0.f, ps = 0.f;
        const unsigned* wv = (const unsigned*)&w0;   // w0 then w1
        #pragma unroll
        for (int u = 0; u < 8; u++) {
            unsigned bits = (u < 4) ? ((const unsigned*)&w0)[u]
                                    : ((const unsigned*)&w1)[u - 4];
            float2 hv = __half22float2(*(const half2*)&bits);
            int col = q * 16 + u * 2;
            pd = fmaf(hv.x, KAs[col],             fmaf(hv.y, KAs[col + 1],             pd));
            ps = fmaf(hv.x, KAs[UNITS + col],     fmaf(hv.y, KAs[UNITS + col + 1],     ps));
        }
        (void)wv;
        #pragma unroll
        for (int o = 2; o > 0; o >>= 1) {
            pd += __shfl_down_sync(0xffffffffu, pd, o, 4);
            ps += __shfl_down_sync(0xffffffffu, ps, o, 4);
        }
        if (q == 0 && gr < N_NODES) {
            g_adst[gr] = pd;
            g_asrc[gr] = ps;
        }
    }
}

// ---------------------------------------------------------------------------
// Kernel 2: fused score + gather. One warp per node, 8 warps/block.
// Per 128-edge tile: pass A (lanes compute p -> smem, src -> smem, partial
// sum), pass B (serial walk over smem tile, warp gathers h16 rows).
// out = (sum p*h) / (sum p).
// ---------------------------------------------------------------------------
__global__ void __launch_bounds__(256)
gat_gather_kernel(float* __restrict__ out)
{
    __shared__ float p_buf[8][128];
    __shared__ int   s_buf[8][128];

    const int wid  = threadIdx.x >> 5;
    const int lane = threadIdx.x & 31;
    const int node = blockIdx.x * 8 + wid;
    if (node >= N_NODES) return;

    const int start = g_rowptr[node];
    const int end   = g_rowptr[node + 1];
    const float ad  = g_adst[node];

    float2 a = make_float2(0.f, 0.f);
    float sum = 0.f;
    const size_t off = 2 * lane;

    for (int ts = start; ts < end; ts += 128) {
        const int nt = min(128, end - ts);
        // pass A: scores into smem
        for (int j = lane; j < nt; j += 32) {
            int s = g_src[ts + j];
            s_buf[wid][j] = s;
            float sc = ad + g_asrc[s];
            sc = (sc > 0.f) ? sc : 0.2f * sc;          // leaky_relu(0.2)
            float p = __expf(fminf(fmaxf(sc, -2.f), 2.f));
            p_buf[wid][j] = p;
            sum += p;
        }
        __syncwarp();
        // pass B: gather
        int j = 0;
        for (; j + 4 <= nt; j += 4) {
            int s0 = s_buf[wid][j],     s1 = s_buf[wid][j + 1];
            int s2 = s_buf[wid][j + 2], s3 = s_buf[wid][j + 3];
            float p0 = p_buf[wid][j],     p1 = p_buf[wid][j + 1];
            float p2 = p_buf[wid][j + 2], p3 = p_buf[wid][j + 3];
            float2 h0 = __half22float2(*(const half2*)&g_h16[(size_t)s0 * UNITS + off]);
            float2 h1 = __half22float2(*(const half2*)&g_h16[(size_t)s1 * UNITS + off]);
            float2 h2 = __half22float2(*(const half2*)&g_h16[(size_t)s2 * UNITS + off]);
            float2 h3 = __half22float2(*(const half2*)&g_h16[(size_t)s3 * UNITS + off]);
            a.x = fmaf(h0.x, p0, a.x);  a.y = fmaf(h0.y, p0, a.y);
            a.x = fmaf(h1.x, p1, a.x);  a.y = fmaf(h1.y, p1, a.y);
            a.x = fmaf(h2.x, p2, a.x);  a.y = fmaf(h2.y, p2, a.y);
            a.x = fmaf(h3.x, p3, a.x);  a.y = fmaf(h3.y, p3, a.y);
        }
        for (; j < nt; j++) {
            int s = s_buf[wid][j];
            float p = p_buf[wid][j];
            float2 h0 = __half22float2(*(const half2*)&g_h16[(size_t)s * UNITS + off]);
            a.x = fmaf(h0.x, p, a.x);
            a.y = fmaf(h0.y, p, a.y);
        }
        __syncwarp();
    }

    #pragma unroll
    for (int o = 16; o > 0; o >>= 1)
        sum += __shfl_xor_sync(0xffffffffu, sum, o);

    float inv = (end > start) ? (1.f / sum) : 0.f;
    float2 r = make_float2(a.x * inv, a.y * inv);
    *(float2*)&out[(size_t)node * UNITS + off] = r;
}

// ---------------------------------------------------------------------------
extern "C" void kernel_launch(void* const* d_in, const int* in_sizes, int n_in,
                              void* d_out, int out_size)
{
    const float*        X   = (const float*)d_in[0];
    const unsigned int* E32 = (const unsigned int*)d_in[1];
    const float*        K   = (const float*)d_in[2];
    const float*        KA  = (const float*)d_in[3];
    float*              O   = (float*)d_out;

    gat_detect_kernel<<<1, 32>>>(E32);
    gat_prep_bt<<<(UNITS * IN_FEAT / 2 + 255) / 256, 256>>>(K);
    gat_unpack_rowptr_kernel<<<(N_EDGES + 255) / 256, 256>>>(E32);
    gat_gemm_kernel<<<(N_NODES + MT - 1) / MT, 256>>>(X, KA);
    gat_gather_kernel<<<(N_NODES + 7) / 8, 256>>>(O);
}